// round 6
// baseline (speedup 1.0000x reference)
#include <cuda_runtime.h>
#include <cuda_bf16.h>

// Problem constants (match reference_code)
#define B_    256
#define PER_  1024
#define NIN_  256
#define NOUT_ (PER_ - NIN_)
#define K_    32
#define E_    (B_ * NIN_ * K_)      // 2,097,152

#define TPB_  256
#define WPB_  8                      // warps per block
#define TGT_PER_WARP 2
#define TGT_PER_BLOCK (WPB_ * TGT_PER_WARP)    // 16
#define BPB_  (NIN_ / TGT_PER_BLOCK)           // 16 blocks per batch
#define GRID_ (B_ * BPB_)                      // 4096

typedef unsigned long long u64;

// ---- packed f32x2 helpers ----
__device__ __forceinline__ u64 pack2(float lo, float hi) {
    u64 r; asm("mov.b64 %0, {%1, %2};" : "=l"(r) : "f"(lo), "f"(hi)); return r;
}
__device__ __forceinline__ void unpack2(u64 v, float& lo, float& hi) {
    asm("mov.b64 {%0, %1}, %2;" : "=f"(lo), "=f"(hi) : "l"(v));
}
__device__ __forceinline__ u64 add2(u64 a, u64 b) {
    u64 r; asm("add.rn.f32x2 %0, %1, %2;" : "=l"(r) : "l"(a), "l"(b)); return r;
}
__device__ __forceinline__ u64 mul2(u64 a, u64 b) {
    u64 r; asm("mul.rn.f32x2 %0, %1, %2;" : "=l"(r) : "l"(a), "l"(b)); return r;
}
__device__ __forceinline__ u64 fma2(u64 a, u64 b, u64 c) {
    u64 r; asm("fma.rn.f32x2 %0, %1, %2, %3;" : "=l"(r) : "l"(a), "l"(b), "l"(c)); return r;
}
__device__ __forceinline__ float sqrt_approx(float x) {
    float r; asm("sqrt.approx.f32 %0, %1;" : "=f"(r) : "f"(x)); return r;
}

// validity: d = sqrt(d2) < 6  <=>  d2 < 36 (monotone sqrt, sqrt(36)=6 exact)

__global__ void __launch_bounds__(TPB_, 6)
mo3enet_knn_dual6_kernel(const float* __restrict__ pos, float* __restrict__ out) {
    // NEGATED coords, pair-packed: slot[(j>>6)*32 + (j&31)] word[(j>>5)&1] = -c[j]
    __shared__ u64      snx[PER_ / 2];            // 4 KB
    __shared__ u64      sny[PER_ / 2];            // 4 KB
    __shared__ u64      snz[PER_ / 2];            // 4 KB
    __shared__ unsigned smask[WPB_][TGT_PER_WARP][32];   // 2 KB ballots
    __shared__ float2   sbuf[WPB_][TGT_PER_WARP][96];    // 12 KB slots {d2|-1, j}

    const int b    = blockIdx.x / BPB_;
    const int grp  = blockIdx.x % BPB_;
    const int tid  = threadIdx.x;
    const int warp = tid >> 5;
    const int lane = tid & 31;

    // ---- stage batch positions (negated) into pair-packed SoA ----
    const float* p = pos + (size_t)b * PER_ * 3;
    for (int j = tid; j < PER_; j += TPB_) {
        float x = p[3 * j + 0], y = p[3 * j + 1], z = p[3 * j + 2];
        int idx = ((j >> 6) << 5) + (j & 31);
        int hw  = (j >> 5) & 1;
        ((float*)snx)[2 * idx + hw] = -x;
        ((float*)sny)[2 * idx + hw] = -y;
        ((float*)snz)[2 * idx + hw] = -z;
    }
    __syncthreads();

    // this warp's two targets
    const int iA = grp * TGT_PER_BLOCK + warp * TGT_PER_WARP;
    const int iB = iA + 1;
    const int goff = b * PER_;
    const unsigned lt = (1u << lane) - 1u;

    u64 xiA2, yiA2, ziA2, xiB2, yiB2, ziB2;
    {
        int ia = ((iA >> 6) << 5) + (iA & 31), ha = (iA >> 5) & 1;
        float xa = -((float*)snx)[2 * ia + ha];
        float ya = -((float*)sny)[2 * ia + ha];
        float za = -((float*)snz)[2 * ia + ha];
        int ib = ((iB >> 6) << 5) + (iB & 31), hb = (iB >> 5) & 1;
        float xb = -((float*)snx)[2 * ib + hb];
        float yb = -((float*)sny)[2 * ib + hb];
        float zb = -((float*)snz)[2 * ib + hb];
        xiA2 = pack2(xa, xa); yiA2 = pack2(ya, ya); ziA2 = pack2(za, za);
        xiB2 = pack2(xb, xb); yiB2 = pack2(yb, yb); ziB2 = pack2(zb, zb);
    }

    const int baseA = (b * NIN_ + iA) * K_ + lane;
    const int baseB = (b * NIN_ + iB) * K_ + lane;

    // ==================== edge set 1: in -> in (j in [0,256)) ================
    {
        unsigned cntA = 0, cntB = 0;
#pragma unroll
        for (int t = 0; t < NIN_ / 64; t++) {
            u64 cx = snx[t * 32 + lane];
            u64 cy = sny[t * 32 + lane];
            u64 cz = snz[t * 32 + lane];
            const int j0 = t * 64 + lane;
            const int j1 = t * 64 + 32 + lane;
            // target A
            if (cntA < K_) {
                u64 dx = add2(xiA2, cx), dy = add2(yiA2, cy), dz = add2(ziA2, cz);
                u64 s  = fma2(dx, dx, fma2(dy, dy, mul2(dz, dz)));
                float lo, hi; unpack2(s, lo, hi);
                bool v0 = (lo < 36.0f) && (j0 != iA);
                bool v1 = (hi < 36.0f) && (j1 != iA);
                unsigned m0 = __ballot_sync(0xffffffffu, v0);
                unsigned m1 = __ballot_sync(0xffffffffu, v1);
                if (lane == 0)
                    *(u64*)&smask[warp][0][2 * t] = ((u64)m1 << 32) | (u64)m0;
                unsigned s0 = cntA + __popc(m0 & lt);                 // < 96
                if (v0) sbuf[warp][0][s0] = make_float2(lo, __int_as_float(j0));
                unsigned pm0 = __popc(m0);
                unsigned s1 = cntA + pm0 + __popc(m1 & lt);           // < 96
                if (v1) sbuf[warp][0][s1] = make_float2(hi, __int_as_float(j1));
                cntA += pm0 + __popc(m1);
            }
            // target B
            if (cntB < K_) {
                u64 dx = add2(xiB2, cx), dy = add2(yiB2, cy), dz = add2(ziB2, cz);
                u64 s  = fma2(dx, dx, fma2(dy, dy, mul2(dz, dz)));
                float lo, hi; unpack2(s, lo, hi);
                bool v0 = (lo < 36.0f) && (j0 != iB);
                bool v1 = (hi < 36.0f) && (j1 != iB);
                unsigned m0 = __ballot_sync(0xffffffffu, v0);
                unsigned m1 = __ballot_sync(0xffffffffu, v1);
                if (lane == 0)
                    *(u64*)&smask[warp][1][2 * t] = ((u64)m1 << 32) | (u64)m0;
                unsigned s0 = cntB + __popc(m0 & lt);
                if (v0) sbuf[warp][1][s0] = make_float2(lo, __int_as_float(j0));
                unsigned pm0 = __popc(m0);
                unsigned s1 = cntB + pm0 + __popc(m1 & lt);
                if (v1) sbuf[warp][1][s1] = make_float2(hi, __int_as_float(j1));
                cntB += pm0 + __popc(m1);
            }
        }
        // padding + emit, per target (warp-uniform control)
#pragma unroll
        for (int T = 0; T < 2; T++) {
            unsigned cnt = T ? cntB : cntA;
            if (cnt < K_) {
                unsigned c = cnt;
                for (int w = 0; c < K_; w++) {
                    unsigned m = ~smask[warp][T][w];
                    unsigned sl = c + __popc(m & lt);
                    if (((m >> lane) & 1u) && sl < K_)
                        sbuf[warp][T][sl] = make_float2(-1.0f, __int_as_float(32 * w + lane));
                    c += __popc(m);
                }
            }
            __syncwarp();
            float2 v = sbuf[warp][T][lane];
            int j = __float_as_int(v.y);
            bool val = (v.x >= 0.0f);
            int base = T ? baseB : baseA;
            out[0 * E_ + base] = (float)(goff + j);
            out[1 * E_ + base] = (float)(goff + (T ? iB : iA));
            out[2 * E_ + base] = val ? 1.0f : 0.0f;
            out[3 * E_ + base] = val ? sqrt_approx(v.x) : 0.0f;
        }
        __syncwarp();   // sbuf/smask reused below
    }

    // ==================== edge set 2: in -> out (j in [256,1024)) ============
    {
        unsigned cntA = 0, cntB = 0;
#pragma unroll 4
        for (int t = 0; t < NOUT_ / 64; t++) {
            u64 cx = snx[(NIN_ / 2) + t * 32 + lane];
            u64 cy = sny[(NIN_ / 2) + t * 32 + lane];
            u64 cz = snz[(NIN_ / 2) + t * 32 + lane];
            const int j0 = NIN_ + t * 64 + lane;
            const int j1 = NIN_ + t * 64 + 32 + lane;
            // target A
            if (cntA < K_) {
                u64 dx = add2(xiA2, cx), dy = add2(yiA2, cy), dz = add2(ziA2, cz);
                u64 s  = fma2(dx, dx, fma2(dy, dy, mul2(dz, dz)));
                float lo, hi; unpack2(s, lo, hi);
                bool v0 = (lo < 36.0f);
                bool v1 = (hi < 36.0f);
                unsigned m0 = __ballot_sync(0xffffffffu, v0);
                unsigned m1 = __ballot_sync(0xffffffffu, v1);
                if (lane == 0)
                    *(u64*)&smask[warp][0][2 * t] = ((u64)m1 << 32) | (u64)m0;
                unsigned s0 = cntA + __popc(m0 & lt);
                if (v0) sbuf[warp][0][s0] = make_float2(lo, __int_as_float(j0));
                unsigned pm0 = __popc(m0);
                unsigned s1 = cntA + pm0 + __popc(m1 & lt);
                if (v1) sbuf[warp][0][s1] = make_float2(hi, __int_as_float(j1));
                cntA += pm0 + __popc(m1);
            }
            // target B
            if (cntB < K_) {
                u64 dx = add2(xiB2, cx), dy = add2(yiB2, cy), dz = add2(ziB2, cz);
                u64 s  = fma2(dx, dx, fma2(dy, dy, mul2(dz, dz)));
                float lo, hi; unpack2(s, lo, hi);
                bool v0 = (lo < 36.0f);
                bool v1 = (hi < 36.0f);
                unsigned m0 = __ballot_sync(0xffffffffu, v0);
                unsigned m1 = __ballot_sync(0xffffffffu, v1);
                if (lane == 0)
                    *(u64*)&smask[warp][1][2 * t] = ((u64)m1 << 32) | (u64)m0;
                unsigned s0 = cntB + __popc(m0 & lt);
                if (v0) sbuf[warp][1][s0] = make_float2(lo, __int_as_float(j0));
                unsigned pm0 = __popc(m0);
                unsigned s1 = cntB + pm0 + __popc(m1 & lt);
                if (v1) sbuf[warp][1][s1] = make_float2(hi, __int_as_float(j1));
                cntB += pm0 + __popc(m1);
            }
        }
#pragma unroll
        for (int T = 0; T < 2; T++) {
            unsigned cnt = T ? cntB : cntA;
            if (cnt < K_) {
                unsigned c = cnt;
                for (int w = 0; c < K_; w++) {
                    unsigned m = ~smask[warp][T][w];
                    unsigned sl = c + __popc(m & lt);
                    if (((m >> lane) & 1u) && sl < K_)
                        sbuf[warp][T][sl] = make_float2(-1.0f, __int_as_float(NIN_ + 32 * w + lane));
                    c += __popc(m);
                }
            }
            __syncwarp();
            float2 v = sbuf[warp][T][lane];
            int j = __float_as_int(v.y);
            bool val = (v.x >= 0.0f);
            int base = T ? baseB : baseA;
            out[4 * E_ + base] = (float)(goff + j);
            out[5 * E_ + base] = (float)(goff + (T ? iB : iA));
            out[6 * E_ + base] = val ? 1.0f : 0.0f;
            out[7 * E_ + base] = val ? sqrt_approx(v.x) : 0.0f;
        }
    }
}

extern "C" void kernel_launch(void* const* d_in, const int* in_sizes, int n_in,
                              void* d_out, int out_size) {
    const float* pos = (const float*)d_in[0];   // [N, 3] float32
    float* out = (float*)d_out;
    mo3enet_knn_dual6_kernel<<<GRID_, TPB_>>>(pos, out);
}

// round 7
// speedup vs baseline: 1.0927x; 1.0927x over previous
#include <cuda_runtime.h>
#include <cuda_bf16.h>

// Problem constants (match reference_code)
#define B_    256
#define PER_  1024
#define NIN_  256
#define NOUT_ (PER_ - NIN_)
#define K_    32
#define E_    (B_ * NIN_ * K_)      // 2,097,152

#define TPB_  256
#define WPB_  8                      // warps per block
#define TGT_PER_WARP 2
#define TGT_PER_BLOCK (WPB_ * TGT_PER_WARP)    // 16
#define BPB_  (NIN_ / TGT_PER_BLOCK)           // 16 blocks per batch
#define GRID_ (B_ * BPB_)                      // 4096

typedef unsigned long long u64;

// ---- packed f32x2 helpers ----
__device__ __forceinline__ u64 pack2(float lo, float hi) {
    u64 r; asm("mov.b64 %0, {%1, %2};" : "=l"(r) : "f"(lo), "f"(hi)); return r;
}
__device__ __forceinline__ void unpack2(u64 v, float& lo, float& hi) {
    asm("mov.b64 {%0, %1}, %2;" : "=f"(lo), "=f"(hi) : "l"(v));
}
__device__ __forceinline__ u64 add2(u64 a, u64 b) {
    u64 r; asm("add.rn.f32x2 %0, %1, %2;" : "=l"(r) : "l"(a), "l"(b)); return r;
}
__device__ __forceinline__ u64 mul2(u64 a, u64 b) {
    u64 r; asm("mul.rn.f32x2 %0, %1, %2;" : "=l"(r) : "l"(a), "l"(b)); return r;
}
__device__ __forceinline__ u64 fma2(u64 a, u64 b, u64 c) {
    u64 r; asm("fma.rn.f32x2 %0, %1, %2, %3;" : "=l"(r) : "l"(a), "l"(b), "l"(c)); return r;
}
__device__ __forceinline__ float sqrt_approx(float x) {
    float r; asm("sqrt.approx.f32 %0, %1;" : "=f"(r) : "f"(x)); return r;
}

// validity: d = sqrt(d2) < 6  <=>  d2 < 36 (monotone sqrt, sqrt(36)=6 exact)

__global__ void __launch_bounds__(TPB_, 4)
mo3enet_knn_dual_kernel(const float* __restrict__ pos, float* __restrict__ out) {
    // NEGATED coords, pair-packed: slot[(j>>6)*32 + (j&31)] word[(j>>5)&1] = -c[j]
    __shared__ u64      snx[PER_ / 2];            // 4 KB
    __shared__ u64      sny[PER_ / 2];            // 4 KB
    __shared__ u64      snz[PER_ / 2];            // 4 KB
    __shared__ unsigned smask[WPB_][TGT_PER_WARP][32];   // 2 KB ballots
    __shared__ float2   sbuf[WPB_][TGT_PER_WARP][64];    // 8 KB slots {d2|-1, j}

    const int b    = blockIdx.x / BPB_;
    const int grp  = blockIdx.x % BPB_;
    const int tid  = threadIdx.x;
    const int warp = tid >> 5;
    const int lane = tid & 31;

    // ---- stage batch positions (negated) into pair-packed SoA ----
    const float* p = pos + (size_t)b * PER_ * 3;
    for (int j = tid; j < PER_; j += TPB_) {
        float x = p[3 * j + 0], y = p[3 * j + 1], z = p[3 * j + 2];
        int idx = ((j >> 6) << 5) + (j & 31);
        int hw  = (j >> 5) & 1;
        ((float*)snx)[2 * idx + hw] = -x;
        ((float*)sny)[2 * idx + hw] = -y;
        ((float*)snz)[2 * idx + hw] = -z;
    }
    __syncthreads();

    // this warp's two targets
    const int iA = grp * TGT_PER_BLOCK + warp * TGT_PER_WARP;
    const int iB = iA + 1;
    const int goff = b * PER_;
    const unsigned lt = (1u << lane) - 1u;

    u64 xiA2, yiA2, ziA2, xiB2, yiB2, ziB2;
    {
        int ia = ((iA >> 6) << 5) + (iA & 31), ha = (iA >> 5) & 1;
        float xa = -((float*)snx)[2 * ia + ha];
        float ya = -((float*)sny)[2 * ia + ha];
        float za = -((float*)snz)[2 * ia + ha];
        int ib = ((iB >> 6) << 5) + (iB & 31), hb = (iB >> 5) & 1;
        float xb = -((float*)snx)[2 * ib + hb];
        float yb = -((float*)sny)[2 * ib + hb];
        float zb = -((float*)snz)[2 * ib + hb];
        xiA2 = pack2(xa, xa); yiA2 = pack2(ya, ya); ziA2 = pack2(za, za);
        xiB2 = pack2(xb, xb); yiB2 = pack2(yb, yb); ziB2 = pack2(zb, zb);
    }

    const int baseA = (b * NIN_ + iA) * K_ + lane;
    const int baseB = (b * NIN_ + iB) * K_ + lane;

    // ==================== edge set 1: in -> in (j in [0,256)) ================
    {
        unsigned cntA = 0, cntB = 0;
#pragma unroll
        for (int t = 0; t < NIN_ / 64; t++) {
            u64 cx = snx[t * 32 + lane];
            u64 cy = sny[t * 32 + lane];
            u64 cz = snz[t * 32 + lane];
            const int j0 = t * 64 + lane;
            const int j1 = t * 64 + 32 + lane;
            // target A
            {
                u64 dx = add2(xiA2, cx), dy = add2(yiA2, cy), dz = add2(ziA2, cz);
                u64 s  = fma2(dx, dx, fma2(dy, dy, mul2(dz, dz)));
                float lo, hi; unpack2(s, lo, hi);
                bool v0 = (lo < 36.0f) && (j0 != iA);
                bool v1 = (hi < 36.0f) && (j1 != iA);
                unsigned m0 = __ballot_sync(0xffffffffu, v0);
                unsigned m1 = __ballot_sync(0xffffffffu, v1);
                if (lane == 0)
                    *(u64*)&smask[warp][0][2 * t] = ((u64)m1 << 32) | (u64)m0;
                unsigned s0 = min(cntA + __popc(m0 & lt), 63u);
                if (v0) sbuf[warp][0][s0] = make_float2(lo, __int_as_float(j0));
                cntA += __popc(m0);
                unsigned s1 = min(cntA + __popc(m1 & lt), 63u);
                if (v1) sbuf[warp][0][s1] = make_float2(hi, __int_as_float(j1));
                cntA += __popc(m1);
            }
            // target B
            {
                u64 dx = add2(xiB2, cx), dy = add2(yiB2, cy), dz = add2(ziB2, cz);
                u64 s  = fma2(dx, dx, fma2(dy, dy, mul2(dz, dz)));
                float lo, hi; unpack2(s, lo, hi);
                bool v0 = (lo < 36.0f) && (j0 != iB);
                bool v1 = (hi < 36.0f) && (j1 != iB);
                unsigned m0 = __ballot_sync(0xffffffffu, v0);
                unsigned m1 = __ballot_sync(0xffffffffu, v1);
                if (lane == 0)
                    *(u64*)&smask[warp][1][2 * t] = ((u64)m1 << 32) | (u64)m0;
                unsigned s0 = min(cntB + __popc(m0 & lt), 63u);
                if (v0) sbuf[warp][1][s0] = make_float2(lo, __int_as_float(j0));
                cntB += __popc(m0);
                unsigned s1 = min(cntB + __popc(m1 & lt), 63u);
                if (v1) sbuf[warp][1][s1] = make_float2(hi, __int_as_float(j1));
                cntB += __popc(m1);
            }
        }
        // padding + emit, per target (warp-uniform control)
#pragma unroll
        for (int T = 0; T < 2; T++) {
            unsigned cnt = T ? cntB : cntA;
            if (cnt < K_) {
                unsigned c = cnt;
                for (int w = 0; c < K_; w++) {
                    unsigned m = ~smask[warp][T][w];
                    unsigned sl = c + __popc(m & lt);
                    if (((m >> lane) & 1u) && sl < K_)
                        sbuf[warp][T][sl] = make_float2(-1.0f, __int_as_float(32 * w + lane));
                    c += __popc(m);
                }
            }
            __syncwarp();
            float2 v = sbuf[warp][T][lane];
            int j = __float_as_int(v.y);
            bool val = (v.x >= 0.0f);
            int base = T ? baseB : baseA;
            out[0 * E_ + base] = (float)(goff + j);
            out[1 * E_ + base] = (float)(goff + (T ? iB : iA));
            out[2 * E_ + base] = val ? 1.0f : 0.0f;
            out[3 * E_ + base] = val ? sqrt_approx(v.x) : 0.0f;
        }
        __syncwarp();   // sbuf/smask reused below
    }

    // ==================== edge set 2: in -> out (j in [256,1024)) ============
    {
        unsigned cntA = 0, cntB = 0;
#pragma unroll
        for (int t = 0; t < NOUT_ / 64; t++) {
            int ps = (NIN_ / 2) + t * 32 + lane;
            u64 cx = snx[ps];
            u64 cy = sny[ps];
            u64 cz = snz[ps];
            const int j0 = NIN_ + t * 64 + lane;
            const int j1 = NIN_ + t * 64 + 32 + lane;
            // target A
            {
                u64 dx = add2(xiA2, cx), dy = add2(yiA2, cy), dz = add2(ziA2, cz);
                u64 s  = fma2(dx, dx, fma2(dy, dy, mul2(dz, dz)));
                float lo, hi; unpack2(s, lo, hi);
                bool v0 = (lo < 36.0f);
                bool v1 = (hi < 36.0f);
                unsigned m0 = __ballot_sync(0xffffffffu, v0);
                unsigned m1 = __ballot_sync(0xffffffffu, v1);
                if (lane == 0)
                    *(u64*)&smask[warp][0][2 * t] = ((u64)m1 << 32) | (u64)m0;
                unsigned s0 = min(cntA + __popc(m0 & lt), 63u);
                if (v0) sbuf[warp][0][s0] = make_float2(lo, __int_as_float(j0));
                cntA += __popc(m0);
                unsigned s1 = min(cntA + __popc(m1 & lt), 63u);
                if (v1) sbuf[warp][0][s1] = make_float2(hi, __int_as_float(j1));
                cntA += __popc(m1);
            }
            // target B
            {
                u64 dx = add2(xiB2, cx), dy = add2(yiB2, cy), dz = add2(ziB2, cz);
                u64 s  = fma2(dx, dx, fma2(dy, dy, mul2(dz, dz)));
                float lo, hi; unpack2(s, lo, hi);
                bool v0 = (lo < 36.0f);
                bool v1 = (hi < 36.0f);
                unsigned m0 = __ballot_sync(0xffffffffu, v0);
                unsigned m1 = __ballot_sync(0xffffffffu, v1);
                if (lane == 0)
                    *(u64*)&smask[warp][1][2 * t] = ((u64)m1 << 32) | (u64)m0;
                unsigned s0 = min(cntB + __popc(m0 & lt), 63u);
                if (v0) sbuf[warp][1][s0] = make_float2(lo, __int_as_float(j0));
                cntB += __popc(m0);
                unsigned s1 = min(cntB + __popc(m1 & lt), 63u);
                if (v1) sbuf[warp][1][s1] = make_float2(hi, __int_as_float(j1));
                cntB += __popc(m1);
            }
        }
#pragma unroll
        for (int T = 0; T < 2; T++) {
            unsigned cnt = T ? cntB : cntA;
            if (cnt < K_) {
                unsigned c = cnt;
                for (int w = 0; c < K_; w++) {
                    unsigned m = ~smask[warp][T][w];
                    unsigned sl = c + __popc(m & lt);
                    if (((m >> lane) & 1u) && sl < K_)
                        sbuf[warp][T][sl] = make_float2(-1.0f, __int_as_float(NIN_ + 32 * w + lane));
                    c += __popc(m);
                }
            }
            __syncwarp();
            float2 v = sbuf[warp][T][lane];
            int j = __float_as_int(v.y);
            bool val = (v.x >= 0.0f);
            int base = T ? baseB : baseA;
            out[4 * E_ + base] = (float)(goff + j);
            out[5 * E_ + base] = (float)(goff + (T ? iB : iA));
            out[6 * E_ + base] = val ? 1.0f : 0.0f;
            out[7 * E_ + base] = val ? sqrt_approx(v.x) : 0.0f;
        }
    }
}

extern "C" void kernel_launch(void* const* d_in, const int* in_sizes, int n_in,
                              void* d_out, int out_size) {
    const float* pos = (const float*)d_in[0];   // [N, 3] float32
    float* out = (float*)d_out;
    mo3enet_knn_dual_kernel<<<GRID_, TPB_>>>(pos, out);
}